// round 5
// baseline (speedup 1.0000x reference)
#include <cuda_runtime.h>

// Problem constants (fixed by the dataset)
#define HH   512
#define WW   512
#define KK   51
#define PADK 25           // K//2
#define PR   562          // padded extent (512 + 2*25)
#define PSTR 576          // padded row stride (16B-aligned float4 rows)
#define HWSZ (512*512)

typedef unsigned long long ull;

// Pre-padded frames: [frame(0/2)][batch][channel][row][col]  (15.5 MB scratch)
__device__ __align__(16) float g_pad[2][2][3][PR][PSTR];

// ---------------------------------------------------------------------------
// Pad kernel: replication-pad both frames into g_pad.
// ---------------------------------------------------------------------------
__global__ void pad_kernel(const float* __restrict__ f0,
                           const float* __restrict__ f2) {
    long idx = (long)blockIdx.x * blockDim.x + threadIdx.x;
    const long total = 2L * 2 * 3 * PR * PSTR;
    if (idx >= total) return;
    int col = (int)(idx % PSTR);
    long r  = idx / PSTR;
    int row = (int)(r % PR); r /= PR;
    int c   = (int)(r % 3);  r /= 3;
    int b   = (int)(r % 2);  r /= 2;
    int f   = (int)r;
    int sy = row - PADK; sy = sy < 0 ? 0 : (sy > HH - 1 ? HH - 1 : sy);
    int sx = col - PADK; sx = sx < 0 ? 0 : (sx > WW - 1 ? WW - 1 : sx);
    const float* src = f ? f2 : f0;
    g_pad[f][b][c][row][col] = src[((size_t)(b * 3 + c) * HH + sy) * WW + sx];
}

// ---------------------------------------------------------------------------
// Packed fp32 helpers (Blackwell f32x2 — PTX only, ptxas never emits it)
// ---------------------------------------------------------------------------
__device__ __forceinline__ ull pk(float lo, float hi) {
    ull r;
    asm("mov.b64 %0, {%1, %2};" : "=l"(r) : "f"(lo), "f"(hi));
    return r;
}
__device__ __forceinline__ void fma2(ull& d, ull a, ull b) {   // d = a*b + d (lanewise)
    asm("fma.rn.f32x2 %0, %1, %2, %0;" : "+l"(d) : "l"(a), "l"(b));
}
__device__ __forceinline__ float2 up(ull v) {
    float2 f;
    asm("mov.b64 {%0, %1}, %2;" : "=f"(f.x), "=f"(f.y) : "l"(v));
    return f;
}

// ---------------------------------------------------------------------------
// cp.async helpers
// ---------------------------------------------------------------------------
__device__ __forceinline__ void cp_async16(void* smem_dst, const void* gmem_src) {
    unsigned saddr = (unsigned)__cvta_generic_to_shared(smem_dst);
    asm volatile("cp.async.cg.shared.global [%0], [%1], 16;\n"
                 :: "r"(saddr), "l"(gmem_src));
}
__device__ __forceinline__ void cp_commit() {
    asm volatile("cp.async.commit_group;\n" ::: "memory");
}
__device__ __forceinline__ void cp_wait1() {
    asm volatile("cp.async.wait_group 1;\n" ::: "memory");
}
__device__ __forceinline__ void cp_wait0() {
    asm volatile("cp.async.wait_group 0;\n" ::: "memory");
}

// Stage one padded row (3 channels x 576 floats = 432 float4) into smem buffer.
__device__ __forceinline__ void stage_row(float (*dst)[PSTR],
                                          const float* __restrict__ padB,
                                          int row, int tid) {
    #pragma unroll
    for (int k = 0; k < 4; k++) {
        int idx = tid + k * 128;               // 0..511, need < 432
        if (idx < 432) {
            int c = idx / 144;                 // 144 float4 per channel row
            int q = idx - c * 144;
            const float4* src = reinterpret_cast<const float4*>(
                padB + ((size_t)c * PR + row) * PSTR) + q;
            cp_async16(&dst[c][q * 4], src);
        }
    }
    cp_commit();
}

__device__ __forceinline__ float hk_comp(float4 v, int t) {
    return (t == 0) ? v.x : (t == 1) ? v.y : (t == 2) ? v.z : v.w;
}

// ---------------------------------------------------------------------------
// One 17-tap horizontal chunk, all 51 vertical taps, 3 channels, 4 outputs,
// computed with packed f32x2 FMAs. P rows staged via 3-deep cp.async ring.
// ---------------------------------------------------------------------------
template<int JBASE>
__device__ __forceinline__ void chunk_pass(
    const float* __restrict__ Hf,
    const float* __restrict__ Vf,
    const float* __restrict__ padB,
    float (*sbuf)[3][PSTR],            // [3][3][PSTR] ring buffer
    int y, int x0, int tid, ull acc2[3][4])
{
    constexpr int PHI = JBASE & 3;                 // misalignment phase (0..2)
    // p2 index range: per t, base_t = (PHI+t - ((PHI+t)&1))/2, uses base_t..base_t+8
    constexpr int MAXP2 = (((PHI + 3) - ((PHI + 3) & 1)) >> 1) + 8;
    constexpr int NLL   = (MAXP2 + 2) / 2;         // ulonglong2 loads (5 or 6)

    // Build packed tap pairs hk2[t][m]: 9 u64 per output t, parity-padded with
    // zeros so every pair stays even-aligned.  even parity: (hk[2m],hk[2m+1]),
    // odd parity: (hk[2m-1],hk[2m]).  Rolling 2-float4 window keeps regs low.
    ull hk2[4][9];
    {
        const float* hb = Hf + (size_t)JBASE * HWSZ + (size_t)y * WW + x0;
        float4 h_prev = make_float4(0.f, 0.f, 0.f, 0.f);   // hk[-1] slot
        #pragma unroll
        for (int m = 0; m < 9; m++) {
            float4 h_a = *reinterpret_cast<const float4*>(hb + (size_t)(2 * m) * HWSZ);
            float4 h_b = (2 * m + 1 < 17)
                ? *reinterpret_cast<const float4*>(hb + (size_t)(2 * m + 1) * HWSZ)
                : make_float4(0.f, 0.f, 0.f, 0.f);
            #pragma unroll
            for (int t = 0; t < 4; t++) {
                if (((PHI + t) & 1) == 0)
                    hk2[t][m] = pk(hk_comp(h_a, t), hk_comp(h_b, t));
                else
                    hk2[t][m] = pk(hk_comp(h_prev, t), hk_comp(h_a, t));
            }
            h_prev = h_b;
        }
    }

    const int col0 = x0 + (JBASE & ~3);            // 16B-aligned window start

    // Prologue: stage rows y and y+1 into ring slots 0,1 (2 groups in flight)
    stage_row(sbuf[0], padB, y, tid);
    stage_row(sbuf[1], padB, y + 1, tid);
    cp_wait1();                                    // slot 0 complete
    __syncthreads();

    #pragma unroll 1
    for (int i = 0; i < KK; i++) {
        const int cur = i % 3;
        const bool more = (i + 2 < KK);
        if (more) stage_row(sbuf[(i + 2) % 3], padB, y + i + 2, tid);

        // V taps for this row (LDG, consumed late -> latency hidden)
        float4 v4 = *reinterpret_cast<const float4*>(
            Vf + (size_t)i * HWSZ + (size_t)y * WW + x0);
        ull vd[4];
        vd[0] = pk(v4.x, v4.x); vd[1] = pk(v4.y, v4.y);
        vd[2] = pk(v4.z, v4.z); vd[3] = pk(v4.w, v4.w);

        #pragma unroll
        for (int c = 0; c < 3; c++) {
            // Window as even-aligned u64 pairs (LDS.128 under the hood)
            const ulonglong2* pr = reinterpret_cast<const ulonglong2*>(
                &sbuf[cur][c][col0]);
            ull p2[2 * NLL];
            #pragma unroll
            for (int q = 0; q < NLL; q++) {
                ulonglong2 t2 = pr[q];
                p2[2 * q]     = t2.x;
                p2[2 * q + 1] = t2.y;
            }

            ull hsum2[4] = {0ull, 0ull, 0ull, 0ull};
            #pragma unroll
            for (int t = 0; t < 4; t++) {
                constexpr int T0 = 0;  // (silence unused warnings pattern)
                const int base = ((PHI + t) - ((PHI + t) & 1)) >> 1;
                #pragma unroll
                for (int m = 0; m < 9; m++)
                    fma2(hsum2[t], p2[base + m], hk2[t][m]);
                (void)T0;
            }
            #pragma unroll
            for (int t = 0; t < 4; t++)
                fma2(acc2[c][t], vd[t], hsum2[t]);
        }

        if (more) cp_wait1();      // next slot landed (ring keeps 2 in flight)
        else      cp_wait0();      // drain tail
        __syncthreads();
    }
}

// ---------------------------------------------------------------------------
// Main kernel: one block per (y, b); 128 threads x 4 outputs = full row.
// ---------------------------------------------------------------------------
__global__ void __launch_bounds__(128, 3) sepconv_kernel(
    const float* __restrict__ V1, const float* __restrict__ H1,
    const float* __restrict__ V2, const float* __restrict__ H2,
    float* __restrict__ out)
{
    __shared__ __align__(16) float sbuf[3][3][PSTR];   // 20.7 KB ring

    const int y   = blockIdx.x;
    const int b   = blockIdx.y;
    const int tid = threadIdx.x;
    const int x0  = tid * 4;

    ull acc2[3][4];
    #pragma unroll
    for (int c = 0; c < 3; c++)
        #pragma unroll
        for (int t = 0; t < 4; t++) acc2[c][t] = 0ull;

    #pragma unroll 1
    for (int f = 0; f < 2; f++) {
        const float* Vf   = (f ? V2 : V1) + (size_t)b * KK * HWSZ;
        const float* Hf   = (f ? H2 : H1) + (size_t)b * KK * HWSZ;
        const float* padB = &g_pad[f][b][0][0][0];
        chunk_pass<0 >(Hf, Vf, padB, sbuf, y, x0, tid, acc2);
        chunk_pass<17>(Hf, Vf, padB, sbuf, y, x0, tid, acc2);
        chunk_pass<34>(Hf, Vf, padB, sbuf, y, x0, tid, acc2);
    }

    // Horizontal fold of the two packed partial sums, then vector store.
    #pragma unroll
    for (int c = 0; c < 3; c++) {
        float2 a0 = up(acc2[c][0]), a1 = up(acc2[c][1]);
        float2 a2 = up(acc2[c][2]), a3 = up(acc2[c][3]);
        float4 o;
        o.x = a0.x + a0.y; o.y = a1.x + a1.y;
        o.z = a2.x + a2.y; o.w = a3.x + a3.y;
        *reinterpret_cast<float4*>(
            out + ((size_t)(b * 3 + c) * HH + y) * WW + x0) = o;
    }
}

// ---------------------------------------------------------------------------
// kernel_launch: inputs are frame0, frame2, V1, H1, V2, H2 (metadata order).
// ---------------------------------------------------------------------------
extern "C" void kernel_launch(void* const* d_in, const int* in_sizes, int n_in,
                              void* d_out, int out_size) {
    const float* frame0 = (const float*)d_in[0];
    const float* frame2 = (const float*)d_in[1];
    const float* V1     = (const float*)d_in[2];
    const float* H1     = (const float*)d_in[3];
    const float* V2     = (const float*)d_in[4];
    const float* H2     = (const float*)d_in[5];
    float* out = (float*)d_out;

    const long total = 2L * 2 * 3 * PR * PSTR;
    pad_kernel<<<(int)((total + 255) / 256), 256>>>(frame0, frame2);

    dim3 grid(HH, 2);
    sepconv_kernel<<<grid, 128>>>(V1, H1, V2, H2, out);
}

// round 6
// speedup vs baseline: 1.5564x; 1.5564x over previous
#include <cuda_runtime.h>

// Problem constants (fixed by the dataset)
#define HH   512
#define WW   512
#define KK   51
#define PADK 25           // K//2
#define PR   562          // padded extent (512 + 2*25)
#define PSTR 576          // padded row stride (16B-aligned float4 rows)
#define HWSZ (512*512)
#define WSPAN 192         // warp-private staged span: 128 outputs + 50 halo, padded

// Pre-padded frames: [frame(0/2)][batch][channel][row][col]  (15.5 MB scratch)
__device__ __align__(16) float g_pad[2][2][3][PR][PSTR];

// ---------------------------------------------------------------------------
// Pad kernel: replication-pad both frames into g_pad.
// ---------------------------------------------------------------------------
__global__ void pad_kernel(const float* __restrict__ f0,
                           const float* __restrict__ f2) {
    long idx = (long)blockIdx.x * blockDim.x + threadIdx.x;
    const long total = 2L * 2 * 3 * PR * PSTR;
    if (idx >= total) return;
    int col = (int)(idx % PSTR);
    long r  = idx / PSTR;
    int row = (int)(r % PR); r /= PR;
    int c   = (int)(r % 3);  r /= 3;
    int b   = (int)(r % 2);  r /= 2;
    int f   = (int)r;
    int sy = row - PADK; sy = sy < 0 ? 0 : (sy > HH - 1 ? HH - 1 : sy);
    int sx = col - PADK; sx = sx < 0 ? 0 : (sx > WW - 1 ? WW - 1 : sx);
    const float* src = f ? f2 : f0;
    g_pad[f][b][c][row][col] = src[((size_t)(b * 3 + c) * HH + sy) * WW + sx];
}

// ---------------------------------------------------------------------------
// cp.async helpers
// ---------------------------------------------------------------------------
__device__ __forceinline__ void cp_async16(void* smem_dst, const void* gmem_src) {
    unsigned saddr = (unsigned)__cvta_generic_to_shared(smem_dst);
    asm volatile("cp.async.cg.shared.global [%0], [%1], 16;\n"
                 :: "r"(saddr), "l"(gmem_src));
}
__device__ __forceinline__ void cp_commit() {
    asm volatile("cp.async.commit_group;\n" ::: "memory");
}
__device__ __forceinline__ void cp_wait1() {
    asm volatile("cp.async.wait_group 1;\n" ::: "memory");
}
__device__ __forceinline__ void cp_wait0() {
    asm volatile("cp.async.wait_group 0;\n" ::: "memory");
}

// Per-thread staging context (all addressing hoisted out of the hot loop).
// Each warp stages 3ch x WSPAN floats = 144 float4 per row; lane handles
// units idx = lane + u*32 (u < nvalid).
struct StageCtx {
    const float* padB;    // &g_pad[f][b][0][0][0]
    float*       sbase;   // &sring[w][0][0][0]
    int gOff[5];          // (c*PR)*PSTR + w*128 + q*4   (floats)
    int sOff[5];          // c*WSPAN + q*4               (floats)
    int nvalid;           // 5 for lane<16, else 4
};

__device__ __forceinline__ void stage_row_w(const StageCtx& st, int slot, int row) {
    float* dst = st.sbase + slot * (3 * WSPAN);
    const float* srcrow = st.padB + (size_t)row * PSTR;
    #pragma unroll
    for (int u = 0; u < 5; u++)
        if (u < st.nvalid)
            cp_async16(dst + st.sOff[u], srcrow + st.gOff[u]);
    cp_commit();
}

__device__ __forceinline__ float comp4(float4 v, int t) {
    return (t == 0) ? v.x : (t == 1) ? v.y : (t == 2) ? v.z : v.w;
}

// ---------------------------------------------------------------------------
// One 17-tap horizontal chunk, all 51 vertical taps, 3 channels, 4 outputs.
// P rows staged through a warp-private 3-slot cp.async ring — no block syncs.
// ---------------------------------------------------------------------------
template<int JBASE>
__device__ __forceinline__ void chunk_pass(
    const float* __restrict__ Hf,
    const float* __restrict__ Vf,
    const StageCtx& st,
    int y, int x0, int lcol, float acc[3][4])
{
    constexpr int PHI = JBASE & 3;                 // misalignment phase
    constexpr int NL  = (PHI + 20 + 3) / 4;        // float4 loads per window

    // 17 taps x 4 outputs of Hk in registers (coalesced LDG.128, reused 51x).
    float4 hk[17];
    #pragma unroll
    for (int j = 0; j < 17; j++)
        hk[j] = *reinterpret_cast<const float4*>(
            Hf + (size_t)(JBASE + j) * HWSZ + (size_t)y * WW + x0);

    const int lcol0 = lcol + (JBASE & ~3);         // aligned local window start

    // Prologue: 2 rows in flight
    stage_row_w(st, 0, y);
    stage_row_w(st, 1, y + 1);
    cp_wait1();                                    // slot 0 landed
    __syncwarp();

    #pragma unroll 1
    for (int i = 0; i < KK; i++) {
        const int  cur  = i % 3;
        const bool more = (i + 2 < KK);
        if (more) stage_row_w(st, (i + 2) % 3, y + i + 2);

        // V taps for this row (LDG.128, consumed late -> latency hidden)
        float4 v4 = *reinterpret_cast<const float4*>(
            Vf + (size_t)i * HWSZ + (size_t)y * WW + x0);

        const float* slotbase = st.sbase + cur * (3 * WSPAN);
        #pragma unroll
        for (int c = 0; c < 3; c++) {
            const float* prow = slotbase + c * WSPAN + lcol0;
            float p[NL * 4];
            #pragma unroll
            for (int q = 0; q < NL; q++) {
                float4 t4 = reinterpret_cast<const float4*>(prow)[q];  // LDS.128
                p[4*q+0] = t4.x; p[4*q+1] = t4.y;
                p[4*q+2] = t4.z; p[4*q+3] = t4.w;
            }
            #pragma unroll
            for (int t = 0; t < 4; t++) {
                float hs = p[PHI + t] * comp4(hk[0], t);
                #pragma unroll
                for (int j = 1; j < 17; j++)
                    hs += p[PHI + t + j] * comp4(hk[j], t);
                acc[c][t] += comp4(v4, t) * hs;
            }
        }

        if (more) cp_wait1(); else cp_wait0();
        __syncwarp();          // warp-scope visibility + slot-reuse safety
    }
}

// ---------------------------------------------------------------------------
// Main kernel: one block per (y, b); 4 independent warps x 32 lanes x 4 outputs.
// ---------------------------------------------------------------------------
__global__ void __launch_bounds__(128, 3) sepconv_kernel(
    const float* __restrict__ V1, const float* __restrict__ H1,
    const float* __restrict__ V2, const float* __restrict__ H2,
    float* __restrict__ out)
{
    __shared__ __align__(16) float sring[4][3][3][WSPAN];   // 27.6 KB

    const int y    = blockIdx.x;
    const int b    = blockIdx.y;
    const int tid  = threadIdx.x;
    const int lane = tid & 31;
    const int w    = tid >> 5;
    const int x0   = tid * 4;        // global output column base
    const int lcol = lane * 4;       // column within warp span

    StageCtx st;
    st.sbase  = &sring[w][0][0][0];
    st.nvalid = (lane < 16) ? 5 : 4;
    #pragma unroll
    for (int u = 0; u < 5; u++) {
        int idx = lane + u * 32;     // 0..143 valid
        int c = idx / 48, q = idx - c * 48;
        st.gOff[u] = c * PR * PSTR + w * 128 + q * 4;
        st.sOff[u] = c * WSPAN + q * 4;
    }

    float acc[3][4];
    #pragma unroll
    for (int c = 0; c < 3; c++)
        #pragma unroll
        for (int t = 0; t < 4; t++) acc[c][t] = 0.0f;

    #pragma unroll 1
    for (int f = 0; f < 2; f++) {
        const float* Vf = (f ? V2 : V1) + (size_t)b * KK * HWSZ;
        const float* Hf = (f ? H2 : H1) + (size_t)b * KK * HWSZ;
        st.padB = &g_pad[f][b][0][0][0];
        chunk_pass<0 >(Hf, Vf, st, y, x0, lcol, acc);
        chunk_pass<17>(Hf, Vf, st, y, x0, lcol, acc);
        chunk_pass<34>(Hf, Vf, st, y, x0, lcol, acc);
    }

    #pragma unroll
    for (int c = 0; c < 3; c++) {
        float4 o;
        o.x = acc[c][0]; o.y = acc[c][1]; o.z = acc[c][2]; o.w = acc[c][3];
        *reinterpret_cast<float4*>(
            out + ((size_t)(b * 3 + c) * HH + y) * WW + x0) = o;
    }
}

// ---------------------------------------------------------------------------
// kernel_launch: inputs are frame0, frame2, V1, H1, V2, H2 (metadata order).
// ---------------------------------------------------------------------------
extern "C" void kernel_launch(void* const* d_in, const int* in_sizes, int n_in,
                              void* d_out, int out_size) {
    const float* frame0 = (const float*)d_in[0];
    const float* frame2 = (const float*)d_in[1];
    const float* V1     = (const float*)d_in[2];
    const float* H1     = (const float*)d_in[3];
    const float* V2     = (const float*)d_in[4];
    const float* H2     = (const float*)d_in[5];
    float* out = (float*)d_out;

    const long total = 2L * 2 * 3 * PR * PSTR;
    pad_kernel<<<(int)((total + 255) / 256), 256>>>(frame0, frame2);

    dim3 grid(HH, 2);
    sepconv_kernel<<<grid, 128>>>(V1, H1, V2, H2, out);
}